// round 8
// baseline (speedup 1.0000x reference)
#include <cuda_runtime.h>
#include <cuda_bf16.h>
#include <cstdint>

#define BDIM 8
#define LDIM 256
#define CDIM 512
#define ODIM 512
#define MTOT (BDIM * LDIM)   // 2048
#define KSPL 1536            // 3*CDIM split-K
#define SROWP 72             // smem row stride (64 + 8 pad) bf16
#define SMAT (64 * SROWP)    // one 64x64 tile in smem (elems)

// -------- scratch (static device globals; no allocation) --------
__device__ __align__(16) __nv_bfloat16 g_xt_s[MTOT * KSPL];   // relu(xt) split [hi,hi,lo]
__device__ __align__(16) __nv_bfloat16 g_xd_s[MTOT * KSPL];   // relu(xd) split [hi,hi,lo]
__device__ __align__(16) __nv_bfloat16 g_Wp_s[CDIM * KSPL];   // Wp^T split [hi,lo,hi]
__device__ __align__(16) __nv_bfloat16 g_Wc_s[CDIM * KSPL];   // Wc^T split [hi,lo,hi]
__device__ __align__(16) __nv_bfloat16 g_pt_s[MTOT * KSPL];   // pt split [hi,hi,lo]
__device__ __align__(16) __nv_bfloat16 g_pc_s[MTOT * KSPL];   // pc split [hi,lo,hi]
__device__ float g_scores[BDIM * LDIM * LDIM];
__device__ float g_Ssum[BDIM];
__device__ float g_cp[BDIM * CDIM];

// -------- transcendentals --------
__device__ __forceinline__ float tanh_mufu(float x) {
    float y;
    asm("tanh.approx.f32 %0, %1;" : "=f"(y) : "f"(x));
    return y;
}
__device__ __forceinline__ float tanh_exact(float x) {
    // 1 - 2/(e^{2|x|}+1), err ~1e-6 (used only for table build)
    float ax = fabsf(x);
    float e = __expf(ax + ax);
    float t = 1.0f - __fdividef(2.0f, e + 1.0f);
    return copysignf(t, x);
}
__device__ __forceinline__ float sigmoid_fast(float x) {
    return __fdividef(1.0f, 1.0f + __expf(-x));
}

// -------- helpers --------
__device__ __forceinline__ uint32_t smem_u32(const void* p) {
    uint32_t a;
    asm("{ .reg .u64 t; cvta.to.shared.u64 t, %1; cvt.u32.u64 %0, t; }" : "=r"(a) : "l"(p));
    return a;
}
__device__ __forceinline__ void ldsm4(uint32_t* r, uint32_t addr) {
    asm volatile("ldmatrix.sync.aligned.m8n8.x4.shared.b16 {%0,%1,%2,%3}, [%4];"
                 : "=r"(r[0]), "=r"(r[1]), "=r"(r[2]), "=r"(r[3]) : "r"(addr));
}
__device__ __forceinline__ void mma_bf16(float* c, const uint32_t* a,
                                         uint32_t b0, uint32_t b1) {
    asm volatile(
        "mma.sync.aligned.m16n8k16.row.col.f32.bf16.bf16.f32 "
        "{%0,%1,%2,%3}, {%4,%5,%6,%7}, {%8,%9}, {%0,%1,%2,%3};"
        : "+f"(c[0]), "+f"(c[1]), "+f"(c[2]), "+f"(c[3])
        : "r"(a[0]), "r"(a[1]), "r"(a[2]), "r"(a[3]), "r"(b0), "r"(b1));
}
__device__ __forceinline__ void cp_async16(uint32_t dst, const void* src) {
    asm volatile("cp.async.ca.shared.global [%0], [%1], 16;" :: "r"(dst), "l"(src));
}
#define CP_COMMIT() asm volatile("cp.async.commit_group;" ::: "memory")
#define CP_WAIT1()  asm volatile("cp.async.wait_group 1;" ::: "memory")
#define CP_WAIT0()  asm volatile("cp.async.wait_group 0;" ::: "memory")

__device__ __forceinline__ void split2(float v, unsigned short& h, unsigned short& l) {
    __nv_bfloat16 hb = __float2bfloat16(v);
    __nv_bfloat16 lb = __float2bfloat16(v - __bfloat162float(hb));
    h = __bfloat16_as_ushort(hb);
    l = __bfloat16_as_ushort(lb);
}

// ============================================================
// HMMA 64x64 mainloop over K'=1536, BK=64, 2-stage cp.async pipeline.
// ============================================================
template <int NWM, int NWN, int NT>
__device__ __forceinline__ void hmma_loop64(
        const __nv_bfloat16* __restrict__ A0,
        const __nv_bfloat16* __restrict__ B0,
        __nv_bfloat16* sm, float (*acc)[4], int tid) {
    constexpr int MI = 64 / NWM / 16;
    constexpr int NJ = 64 / NWN / 8;
    constexpr int NJ2 = NJ / 2;
    constexpr int LPT = 1024 / NT;
    constexpr int NCH = KSPL / 64;

    const int lane = tid & 31;
    const int warp = tid >> 5;
    const int wm = warp % NWM;
    const int wn = warp / NWM;
    const uint32_t base = smem_u32(sm);

    auto issue = [&](int s, int c) {
        #pragma unroll
        for (int q = 0; q < LPT; q++) {
            int idx = tid + q * NT;
            int mat = idx >> 9;
            int rem = idx & 511;
            int row = rem >> 3;
            int kq = rem & 7;
            const __nv_bfloat16* g = (mat ? B0 : A0) + (size_t)row * KSPL + c * 64 + kq * 8;
            uint32_t d = base + (uint32_t)((s * 2 + mat) * SMAT + row * SROWP + kq * 8) * 2;
            cp_async16(d, g);
        }
        CP_COMMIT();
    };

    issue(0, 0);

    for (int c = 0; c < NCH; c++) {
        const int s = c & 1;
        if (c + 1 < NCH) {
            issue(s ^ 1, c + 1);
            CP_WAIT1();
        } else {
            CP_WAIT0();
        }
        __syncthreads();

        const uint32_t aBase = base + (uint32_t)(s * 2 * SMAT) * 2;
        const uint32_t bBase = base + (uint32_t)((s * 2 + 1) * SMAT) * 2;
        #pragma unroll
        for (int kk = 0; kk < 64; kk += 16) {
            uint32_t af[MI][4];
            #pragma unroll
            for (int im = 0; im < MI; im++) {
                int row = wm * (64 / NWM) + im * 16 + (lane & 15);
                ldsm4(af[im], aBase + (uint32_t)(row * SROWP + kk + (lane >> 4) * 8) * 2);
            }
            #pragma unroll
            for (int j2 = 0; j2 < NJ2; j2++) {
                uint32_t bfr[4];
                int row = wn * (64 / NWN) + j2 * 16 + (lane & 15);
                ldsm4(bfr, bBase + (uint32_t)(row * SROWP + kk + (lane >> 4) * 8) * 2);
                #pragma unroll
                for (int im = 0; im < MI; im++) {
                    mma_bf16(acc[im * NJ + 2 * j2 + 0], af[im], bfr[0], bfr[2]);
                    mma_bf16(acc[im * NJ + 2 * j2 + 1], af[im], bfr[1], bfr[3]);
                }
            }
        }
        __syncthreads();
    }
}

// ============================================================
// K0: init
// ============================================================
__global__ void init_kernel(const float* __restrict__ bf, float* __restrict__ out) {
    int idx = blockIdx.x * blockDim.x + threadIdx.x;
    if (idx < BDIM) g_Ssum[idx] = 0.0f;
    if (idx < BDIM * CDIM) {
        g_cp[idx] = 0.0f;
        out[idx] = bf[idx & (ODIM - 1)];
    }
}

// ============================================================
// K1: split X (with relu) -> [hi, hi, lo] bf16, K'=1536
// ============================================================
__global__ void split_x_kernel(const float* __restrict__ xt, const float* __restrict__ xd) {
    const float* X = blockIdx.z ? xd : xt;
    __nv_bfloat16* O = blockIdx.z ? g_xd_s : g_xt_s;
    int gid = blockIdx.x * blockDim.x + threadIdx.x;
    if (gid >= MTOT * CDIM / 4) return;
    int m = gid >> 7;
    int k4 = (gid & 127) * 4;
    float4 v = *reinterpret_cast<const float4*>(X + (size_t)m * CDIM + k4);
    float vv[4] = {fmaxf(v.x, 0.f), fmaxf(v.y, 0.f), fmaxf(v.z, 0.f), fmaxf(v.w, 0.f)};
    unsigned short h[4], l[4];
    #pragma unroll
    for (int i = 0; i < 4; i++) split2(vv[i], h[i], l[i]);
    uint2 hp = make_uint2((uint32_t)h[0] | ((uint32_t)h[1] << 16),
                          (uint32_t)h[2] | ((uint32_t)h[3] << 16));
    uint2 lp = make_uint2((uint32_t)l[0] | ((uint32_t)l[1] << 16),
                          (uint32_t)l[2] | ((uint32_t)l[3] << 16));
    size_t base = (size_t)m * KSPL + k4;
    *reinterpret_cast<uint2*>(O + base) = hp;
    *reinterpret_cast<uint2*>(O + base + CDIM) = hp;
    *reinterpret_cast<uint2*>(O + base + 2 * CDIM) = lp;
}

// ============================================================
// K2: split W with transpose: W[k,n] -> Wsplit[n,k'] segs [hi, lo, hi]
// ============================================================
__global__ void split_w_kernel(const float* __restrict__ Wp, const float* __restrict__ Wc) {
    const float* W = blockIdx.z ? Wc : Wp;
    __nv_bfloat16* O = blockIdx.z ? g_Wc_s : g_Wp_s;
    __shared__ float tile[32][33];
    int k0 = blockIdx.x * 32, n0 = blockIdx.y * 32;
    int tx = threadIdx.x, ty = threadIdx.y;
    tile[ty][tx] = W[(size_t)(k0 + ty) * CDIM + n0 + tx];
    __syncthreads();
    float v = tile[tx][ty];
    unsigned short h, l;
    split2(v, h, l);
    size_t base = (size_t)(n0 + ty) * KSPL + k0 + tx;
    O[base] = __ushort_as_bfloat16(h);
    O[base + CDIM] = __ushort_as_bfloat16(l);
    O[base + 2 * CDIM] = __ushort_as_bfloat16(h);
}

// ============================================================
// K3: projection GEMMs (HMMA, 64x64 tiles, 128 thr, 2x2 warps).
// ============================================================
__global__ void __launch_bounds__(128) proj_hmma(const float* __restrict__ bp,
                                                 const float* __restrict__ bc) {
    __shared__ __align__(16) __nv_bfloat16 sm[4 * SMAT];

    const int tid = threadIdx.x;
    const int z = blockIdx.z;
    const int m0 = blockIdx.y * 64;
    const int n0 = blockIdx.x * 64;

    const __nv_bfloat16* X = z ? g_xd_s : g_xt_s;
    const __nv_bfloat16* Wm = z ? g_Wc_s : g_Wp_s;
    const float* bias = z ? bc : bp;
    __nv_bfloat16* P = z ? g_pc_s : g_pt_s;

    float acc[8][4];
    #pragma unroll
    for (int i = 0; i < 8; i++)
        acc[i][0] = acc[i][1] = acc[i][2] = acc[i][3] = 0.0f;

    hmma_loop64<2, 2, 128>(X + (size_t)m0 * KSPL, Wm + (size_t)n0 * KSPL, sm, acc, tid);

    const int lane = tid & 31;
    const int warp = tid >> 5;
    const int wm = warp % 2;
    const int wn = warp / 2;

    #pragma unroll
    for (int im = 0; im < 2; im++) {
        #pragma unroll
        for (int jn = 0; jn < 4; jn++) {
            const float* c = acc[im * 4 + jn];
            int n = n0 + wn * 32 + jn * 8 + (lane & 3) * 2;
            float b0 = __ldg(&bias[n]), b1 = __ldg(&bias[n + 1]);
            int r0 = m0 + wm * 32 + im * 16 + (lane >> 2);
            #pragma unroll
            for (int h = 0; h < 2; h++) {
                int m = r0 + h * 8;
                float v0 = c[2 * h + 0] + b0;
                float v1 = c[2 * h + 1] + b1;
                unsigned short h0, l0, h1, l1;
                split2(v0, h0, l0);
                split2(v1, h1, l1);
                uint32_t hp = (uint32_t)h0 | ((uint32_t)h1 << 16);
                uint32_t lp = (uint32_t)l0 | ((uint32_t)l1 << 16);
                size_t rowoff = (size_t)m * KSPL + n;
                if (z == 0) {
                    *reinterpret_cast<uint32_t*>(P + rowoff) = hp;
                    *reinterpret_cast<uint32_t*>(P + rowoff + CDIM) = hp;
                    *reinterpret_cast<uint32_t*>(P + rowoff + 2 * CDIM) = lp;
                } else {
                    *reinterpret_cast<uint32_t*>(P + rowoff) = hp;
                    *reinterpret_cast<uint32_t*>(P + rowoff + CDIM) = lp;
                    *reinterpret_cast<uint32_t*>(P + rowoff + 2 * CDIM) = hp;
                }
            }
        }
    }
}

// ============================================================
// K4: score GEMM (HMMA, 64x64 tiles, 256 thr, 2x4 warps)
// ============================================================
__global__ void __launch_bounds__(256) score_hmma() {
    __shared__ __align__(16) __nv_bfloat16 sm[4 * SMAT];

    const int tid = threadIdx.x;
    const int b = blockIdx.z;
    const int i0 = blockIdx.y * 64;
    const int j0 = blockIdx.x * 64;

    const __nv_bfloat16* A = g_pt_s + (size_t)(b * LDIM + i0) * KSPL;
    const __nv_bfloat16* B = g_pc_s + (size_t)(b * LDIM + j0) * KSPL;

    float acc[4][4];
    #pragma unroll
    for (int i = 0; i < 4; i++)
        acc[i][0] = acc[i][1] = acc[i][2] = acc[i][3] = 0.0f;

    hmma_loop64<2, 4, 256>(A, B, sm, acc, tid);

    const int lane = tid & 31;
    const int warp = tid >> 5;
    const int wm = warp % 2;
    const int wn = warp / 2;

    float lsum = 0.0f;
    float* Sb = g_scores + ((size_t)b << 16);
    #pragma unroll
    for (int im = 0; im < 2; im++) {
        #pragma unroll
        for (int jn = 0; jn < 2; jn++) {
            const float* c = acc[im * 2 + jn];
            int j = j0 + wn * 16 + jn * 8 + (lane & 3) * 2;
            int r0 = i0 + wm * 32 + im * 16 + (lane >> 2);
            #pragma unroll
            for (int h = 0; h < 2; h++) {
                int i = r0 + h * 8;
                float s0 = sigmoid_fast(c[2 * h + 0]);
                float s1 = sigmoid_fast(c[2 * h + 1]);
                *reinterpret_cast<float2*>(Sb + (size_t)i * LDIM + j) =
                    make_float2(s0, s1);
                lsum += s0 + s1;
            }
        }
    }
    #pragma unroll
    for (int off = 16; off; off >>= 1)
        lsum += __shfl_xor_sync(0xFFFFFFFFu, lsum, off);
    __shared__ float red[8];
    if (lane == 0) red[warp] = lsum;
    __syncthreads();
    if (tid == 0) {
        float s = 0.0f;
        #pragma unroll
        for (int w = 0; w < 8; w++) s += red[w];
        atomicAdd(&g_Ssum[b], s);
    }
}

// ============================================================
// K5: cp_unnorm[b,c] = sum_{i,j} tanh(xd[b,i,c]*xt[b,j,c]) * scores[b,i,j]
// Mixed-pipe tanh: 2/3 via MUFU.TANH, 1/3 via PWL LUT (FMA+ALU+LDS).
// LUT: 256 segments on [0,8]; y = fma(slope, 32*|p|, base); odd-symmetric
// chord error (<=9.4e-5) cancels over the symmetric product distribution.
// ============================================================
__global__ void __launch_bounds__(512) cp_kernel(const float* __restrict__ xd,
                                                 const float* __restrict__ xt) {
    const int b = blockIdx.y;
    const int i0 = blockIdx.x * 4;
    const int c = threadIdx.x;

    __shared__ float4 ws4[LDIM];
    __shared__ float2 tbl[256];

    // build PWL table: segment t covers [t/32, (t+1)/32); y = slope*(32x) + base
    if (threadIdx.x < 256) {
        int t = threadIdx.x;
        float t0 = tanh_exact((float)t * (1.0f / 32.0f));
        float t1 = tanh_exact((float)(t + 1) * (1.0f / 32.0f));
        float slope = t1 - t0;                 // per unit of scaled coord
        float base = t0 - slope * (float)t;
        tbl[t] = make_float2(slope, base);
    }
    {
        float* wsf = reinterpret_cast<float*>(ws4);
        const float* src = g_scores + (size_t)b * LDIM * LDIM + (size_t)i0 * LDIM;
        for (int t = threadIdx.x; t < 4 * LDIM; t += 512) {
            int i = t >> 8, j = t & (LDIM - 1);
            wsf[(j << 2) | i] = src[i * LDIM + j];
        }
    }

    const float* xdp = xd + ((size_t)(b * LDIM + i0)) * CDIM + c;
    const float xd0 = xdp[0 * CDIM];
    const float xd1 = xdp[1 * CDIM];
    const float xd2 = xdp[2 * CDIM];
    const float xd3 = xdp[3 * CDIM];
    __syncthreads();

    // LUT tanh: FMUL(scale,|p|) + FMNMX + F2I + LDS.64 + FFMA + copysign
    auto tanh_lut = [&](float p) -> float {
        float ap32 = fminf(fabsf(p) * 32.0f, 255.0f);
        int idx = (int)ap32;
        float2 sb = tbl[idx];
        float t = fmaf(sb.x, ap32, sb.y);
        return copysignf(t, p);
    };

    const float* xtp = xt + ((size_t)(b * LDIM)) * CDIM + c;
    float acc = 0.0f;
    // groups of 3 j: rotate which rows take the LUT path (4/12 = 1/3)
    #pragma unroll 1
    for (int j = 0; j < 255; j += 3) {
        {   // j+0: LUT rows 0,3
            float xtv = __ldg(&xtp[(size_t)(j + 0) * CDIM]);
            float4 w = ws4[j + 0];
            acc = fmaf(tanh_lut(xd0 * xtv), w.x, acc);
            acc = fmaf(tanh_mufu(xd1 * xtv), w.y, acc);
            acc = fmaf(tanh_mufu(xd2 * xtv), w.z, acc);
            acc = fmaf(tanh_lut(xd3 * xtv), w.w, acc);
        }
        {   // j+1: LUT row 2
            float xtv = __ldg(&xtp[(size_t)(j + 1) * CDIM]);
            float4 w = ws4[j + 1];
            acc = fmaf(tanh_mufu(xd0 * xtv), w.x, acc);
            acc = fmaf(tanh_mufu(xd1 * xtv), w.y, acc);
            acc = fmaf(tanh_lut(xd2 * xtv), w.z, acc);
            acc = fmaf(tanh_mufu(xd3 * xtv), w.w, acc);
        }
        {   // j+2: LUT row 1
            float xtv = __ldg(&xtp[(size_t)(j + 2) * CDIM]);
            float4 w = ws4[j + 2];
            acc = fmaf(tanh_mufu(xd0 * xtv), w.x, acc);
            acc = fmaf(tanh_lut(xd1 * xtv), w.y, acc);
            acc = fmaf(tanh_mufu(xd2 * xtv), w.z, acc);
            acc = fmaf(tanh_mufu(xd3 * xtv), w.w, acc);
        }
    }
    {   // j = 255 tail (255 % 3 == 0 pattern)
        float xtv = __ldg(&xtp[(size_t)255 * CDIM]);
        float4 w = ws4[255];
        acc = fmaf(tanh_lut(xd0 * xtv), w.x, acc);
        acc = fmaf(tanh_mufu(xd1 * xtv), w.y, acc);
        acc = fmaf(tanh_mufu(xd2 * xtv), w.z, acc);
        acc = fmaf(tanh_lut(xd3 * xtv), w.w, acc);
    }
    atomicAdd(&g_cp[b * CDIM + c], acc);
}

// ============================================================
// K6: out[b,o] += (cp[b,:]/S_b) @ Wf[:,o]
// ============================================================
__global__ void out_gemm(const float* __restrict__ Wf, float* __restrict__ out) {
    const int b = blockIdx.x;
    const int c0 = blockIdx.y * 128;
    const int o = threadIdx.x;

    __shared__ float cps[128];
    float inv = __fdividef(1.0f, g_Ssum[b]);
    if (threadIdx.x < 128)
        cps[threadIdx.x] = g_cp[b * CDIM + c0 + threadIdx.x] * inv;
    __syncthreads();

    float acc = 0.0f;
    #pragma unroll 8
    for (int cc = 0; cc < 128; cc++)
        acc = fmaf(cps[cc], Wf[(c0 + cc) * ODIM + o], acc);
    atomicAdd(&out[b * ODIM + o], acc);
}

// ============================================================
extern "C" void kernel_launch(void* const* d_in, const int* in_sizes, int n_in,
                              void* d_out, int out_size) {
    const float* xd = (const float*)d_in[0];
    const float* xt = (const float*)d_in[1];
    const float* Wc = (const float*)d_in[2];
    const float* bc = (const float*)d_in[3];
    const float* Wp = (const float*)d_in[4];
    const float* bp = (const float*)d_in[5];
    const float* Wf = (const float*)d_in[6];
    const float* bf = (const float*)d_in[7];
    float* out = (float*)d_out;

    init_kernel<<<8, 512>>>(bf, out);
    split_x_kernel<<<dim3(MTOT * CDIM / 4 / 256, 1, 2), 256>>>(xt, xd);
    split_w_kernel<<<dim3(16, 16, 2), dim3(32, 32)>>>(Wp, Wc);
    proj_hmma<<<dim3(CDIM / 64, MTOT / 64, 2), 128>>>(bp, bc);
    score_hmma<<<dim3(LDIM / 64, LDIM / 64, BDIM), 256>>>();
    cp_kernel<<<dim3(LDIM / 4, BDIM), 512>>>(xd, xt);
    out_gemm<<<dim3(BDIM, 4), 512>>>(Wf, out);
}

// round 12
// speedup vs baseline: 1.0302x; 1.0302x over previous
#include <cuda_runtime.h>
#include <cuda_bf16.h>
#include <cstdint>

#define BDIM 8
#define LDIM 256
#define CDIM 512
#define ODIM 512
#define MTOT (BDIM * LDIM)   // 2048
#define KSPL 1536            // 3*CDIM split-K
#define SROWP 72             // smem row stride (64 + 8 pad) bf16
#define SMAT (64 * SROWP)    // one 64x64 tile in smem (elems)

// -------- scratch (static device globals; no allocation) --------
__device__ __align__(16) __nv_bfloat16 g_xt_s[MTOT * KSPL];   // relu(xt) split [hi,hi,lo]
__device__ __align__(16) __nv_bfloat16 g_xd_s[MTOT * KSPL];   // relu(xd) split [hi,hi,lo]
__device__ __align__(16) __nv_bfloat16 g_Wp_s[CDIM * KSPL];   // Wp^T split [hi,lo,hi]
__device__ __align__(16) __nv_bfloat16 g_Wc_s[CDIM * KSPL];   // Wc^T split [hi,lo,hi]
__device__ __align__(16) __nv_bfloat16 g_pt_s[MTOT * KSPL];   // pt split [hi,hi,lo]
__device__ __align__(16) __nv_bfloat16 g_pc_s[MTOT * KSPL];   // pc split [hi,lo,hi]
__device__ float g_scores[BDIM * LDIM * LDIM];
__device__ float g_Ssum[BDIM];
__device__ float g_cp[BDIM * CDIM];

// -------- transcendentals --------
__device__ __forceinline__ float tanh_mufu(float x) {
    float y;
    asm("tanh.approx.f32 %0, %1;" : "=f"(y) : "f"(x));
    return y;
}
__device__ __forceinline__ float sigmoid_fast(float x) {
    return __fdividef(1.0f, 1.0f + __expf(-x));
}

// -------- helpers --------
__device__ __forceinline__ uint32_t smem_u32(const void* p) {
    uint32_t a;
    asm("{ .reg .u64 t; cvta.to.shared.u64 t, %1; cvt.u32.u64 %0, t; }" : "=r"(a) : "l"(p));
    return a;
}
__device__ __forceinline__ void ldsm4(uint32_t* r, uint32_t addr) {
    asm volatile("ldmatrix.sync.aligned.m8n8.x4.shared.b16 {%0,%1,%2,%3}, [%4];"
                 : "=r"(r[0]), "=r"(r[1]), "=r"(r[2]), "=r"(r[3]) : "r"(addr));
}
__device__ __forceinline__ void mma_bf16(float* c, const uint32_t* a,
                                         uint32_t b0, uint32_t b1) {
    asm volatile(
        "mma.sync.aligned.m16n8k16.row.col.f32.bf16.bf16.f32 "
        "{%0,%1,%2,%3}, {%4,%5,%6,%7}, {%8,%9}, {%0,%1,%2,%3};"
        : "+f"(c[0]), "+f"(c[1]), "+f"(c[2]), "+f"(c[3])
        : "r"(a[0]), "r"(a[1]), "r"(a[2]), "r"(a[3]), "r"(b0), "r"(b1));
}
__device__ __forceinline__ void cp_async16(uint32_t dst, const void* src) {
    asm volatile("cp.async.ca.shared.global [%0], [%1], 16;" :: "r"(dst), "l"(src));
}
#define CP_COMMIT() asm volatile("cp.async.commit_group;" ::: "memory")
#define CP_WAIT1()  asm volatile("cp.async.wait_group 1;" ::: "memory")
#define CP_WAIT0()  asm volatile("cp.async.wait_group 0;" ::: "memory")

__device__ __forceinline__ void split2(float v, unsigned short& h, unsigned short& l) {
    __nv_bfloat16 hb = __float2bfloat16(v);
    __nv_bfloat16 lb = __float2bfloat16(v - __bfloat162float(hb));
    h = __bfloat16_as_ushort(hb);
    l = __bfloat16_as_ushort(lb);
}

// ============================================================
// HMMA 64x64 mainloop over K'=1536, BK=64, 3-stage cp.async pipeline,
// ONE __syncthreads per chunk. smem: sm[stage][A|B][64*SROWP].
// ============================================================
template <int NWM, int NWN, int NT>
__device__ __forceinline__ void hmma_loop64(
        const __nv_bfloat16* __restrict__ A0,
        const __nv_bfloat16* __restrict__ B0,
        __nv_bfloat16* sm, float (*acc)[4], int tid) {
    constexpr int MI = 64 / NWM / 16;
    constexpr int NJ = 64 / NWN / 8;
    constexpr int NJ2 = NJ / 2;
    constexpr int LPT = 1024 / NT;
    constexpr int NCH = KSPL / 64;      // 24

    const int lane = tid & 31;
    const int warp = tid >> 5;
    const int wm = warp % NWM;
    const int wn = warp / NWM;
    const uint32_t base = smem_u32(sm);

    auto issue = [&](int s, int c) {
        #pragma unroll
        for (int q = 0; q < LPT; q++) {
            int idx = tid + q * NT;
            int mat = idx >> 9;
            int rem = idx & 511;
            int row = rem >> 3;
            int kq = rem & 7;
            const __nv_bfloat16* g = (mat ? B0 : A0) + (size_t)row * KSPL + c * 64 + kq * 8;
            uint32_t d = base + (uint32_t)((s * 2 + mat) * SMAT + row * SROWP + kq * 8) * 2;
            cp_async16(d, g);
        }
        CP_COMMIT();
    };

    issue(0, 0);
    issue(1, 1);

    for (int c = 0; c < NCH; c++) {
        const int s = c % 3;
        // entering: pending groups = {c, c+1(if exists)}
        if (c + 1 < NCH) CP_WAIT1(); else CP_WAIT0();
        __syncthreads();   // chunk c visible to all; compute of c-1 retired by all
        if (c + 2 < NCH) issue((c + 2) % 3, c + 2);   // overwrites stage of c-1: safe

        const uint32_t aBase = base + (uint32_t)(s * 2 * SMAT) * 2;
        const uint32_t bBase = base + (uint32_t)((s * 2 + 1) * SMAT) * 2;
        #pragma unroll
        for (int kk = 0; kk < 64; kk += 16) {
            uint32_t af[MI][4];
            #pragma unroll
            for (int im = 0; im < MI; im++) {
                int row = wm * (64 / NWM) + im * 16 + (lane & 15);
                ldsm4(af[im], aBase + (uint32_t)(row * SROWP + kk + (lane >> 4) * 8) * 2);
            }
            #pragma unroll
            for (int j2 = 0; j2 < NJ2; j2++) {
                uint32_t bfr[4];
                int row = wn * (64 / NWN) + j2 * 16 + (lane & 15);
                ldsm4(bfr, bBase + (uint32_t)(row * SROWP + kk + (lane >> 4) * 8) * 2);
                #pragma unroll
                for (int im = 0; im < MI; im++) {
                    mma_bf16(acc[im * NJ + 2 * j2 + 0], af[im], bfr[0], bfr[2]);
                    mma_bf16(acc[im * NJ + 2 * j2 + 1], af[im], bfr[1], bfr[3]);
                }
            }
        }
    }
    __syncthreads();
}

// ============================================================
// K0: init
// ============================================================
__global__ void init_kernel(const float* __restrict__ bf, float* __restrict__ out) {
    int idx = blockIdx.x * blockDim.x + threadIdx.x;
    if (idx < BDIM) g_Ssum[idx] = 0.0f;
    if (idx < BDIM * CDIM) {
        g_cp[idx] = 0.0f;
        out[idx] = bf[idx & (ODIM - 1)];
    }
}

// ============================================================
// K1: split X (with relu) -> [hi, hi, lo] bf16, K'=1536
// ============================================================
__global__ void split_x_kernel(const float* __restrict__ xt, const float* __restrict__ xd) {
    const float* X = blockIdx.z ? xd : xt;
    __nv_bfloat16* O = blockIdx.z ? g_xd_s : g_xt_s;
    int gid = blockIdx.x * blockDim.x + threadIdx.x;
    if (gid >= MTOT * CDIM / 4) return;
    int m = gid >> 7;
    int k4 = (gid & 127) * 4;
    float4 v = *reinterpret_cast<const float4*>(X + (size_t)m * CDIM + k4);
    float vv[4] = {fmaxf(v.x, 0.f), fmaxf(v.y, 0.f), fmaxf(v.z, 0.f), fmaxf(v.w, 0.f)};
    unsigned short h[4], l[4];
    #pragma unroll
    for (int i = 0; i < 4; i++) split2(vv[i], h[i], l[i]);
    uint2 hp = make_uint2((uint32_t)h[0] | ((uint32_t)h[1] << 16),
                          (uint32_t)h[2] | ((uint32_t)h[3] << 16));
    uint2 lp = make_uint2((uint32_t)l[0] | ((uint32_t)l[1] << 16),
                          (uint32_t)l[2] | ((uint32_t)l[3] << 16));
    size_t base = (size_t)m * KSPL + k4;
    *reinterpret_cast<uint2*>(O + base) = hp;
    *reinterpret_cast<uint2*>(O + base + CDIM) = hp;
    *reinterpret_cast<uint2*>(O + base + 2 * CDIM) = lp;
}

// ============================================================
// K2: split W with transpose: W[k,n] -> Wsplit[n,k'] segs [hi, lo, hi]
// ============================================================
__global__ void split_w_kernel(const float* __restrict__ Wp, const float* __restrict__ Wc) {
    const float* W = blockIdx.z ? Wc : Wp;
    __nv_bfloat16* O = blockIdx.z ? g_Wc_s : g_Wp_s;
    __shared__ float tile[32][33];
    int k0 = blockIdx.x * 32, n0 = blockIdx.y * 32;
    int tx = threadIdx.x, ty = threadIdx.y;
    tile[ty][tx] = W[(size_t)(k0 + ty) * CDIM + n0 + tx];
    __syncthreads();
    float v = tile[tx][ty];
    unsigned short h, l;
    split2(v, h, l);
    size_t base = (size_t)(n0 + ty) * KSPL + k0 + tx;
    O[base] = __ushort_as_bfloat16(h);
    O[base + CDIM] = __ushort_as_bfloat16(l);
    O[base + 2 * CDIM] = __ushort_as_bfloat16(h);
}

// ============================================================
// K3: projection GEMMs (HMMA, 64x64 tiles, 256 thr, 2x4 warps, 3-stage).
// z=0: pt -> g_pt_s [hi,hi,lo] ; z=1: pc -> g_pc_s [hi,lo,hi]
// ============================================================
__global__ void __launch_bounds__(256) proj_hmma(const float* __restrict__ bp,
                                                 const float* __restrict__ bc) {
    __shared__ __align__(16) __nv_bfloat16 sm[6 * SMAT];   // 3 stages x {A,B}

    const int tid = threadIdx.x;
    const int z = blockIdx.z;
    const int m0 = blockIdx.y * 64;
    const int n0 = blockIdx.x * 64;

    const __nv_bfloat16* X = z ? g_xd_s : g_xt_s;
    const __nv_bfloat16* Wm = z ? g_Wc_s : g_Wp_s;
    const float* bias = z ? bc : bp;
    __nv_bfloat16* P = z ? g_pc_s : g_pt_s;

    float acc[4][4];   // MI=2, NJ=2
    #pragma unroll
    for (int i = 0; i < 4; i++)
        acc[i][0] = acc[i][1] = acc[i][2] = acc[i][3] = 0.0f;

    hmma_loop64<2, 4, 256>(X + (size_t)m0 * KSPL, Wm + (size_t)n0 * KSPL, sm, acc, tid);

    const int lane = tid & 31;
    const int warp = tid >> 5;
    const int wm = warp % 2;
    const int wn = warp / 2;    // 0..3

    #pragma unroll
    for (int im = 0; im < 2; im++) {
        #pragma unroll
        for (int jn = 0; jn < 2; jn++) {
            const float* c = acc[im * 2 + jn];
            int n = n0 + wn * 16 + jn * 8 + (lane & 3) * 2;
            float b0 = __ldg(&bias[n]), b1 = __ldg(&bias[n + 1]);
            int r0 = m0 + wm * 32 + im * 16 + (lane >> 2);
            #pragma unroll
            for (int h = 0; h < 2; h++) {
                int m = r0 + h * 8;
                float v0 = c[2 * h + 0] + b0;
                float v1 = c[2 * h + 1] + b1;
                unsigned short h0, l0, h1, l1;
                split2(v0, h0, l0);
                split2(v1, h1, l1);
                uint32_t hp = (uint32_t)h0 | ((uint32_t)h1 << 16);
                uint32_t lp = (uint32_t)l0 | ((uint32_t)l1 << 16);
                size_t rowoff = (size_t)m * KSPL + n;
                if (z == 0) {   // pt: [hi, hi, lo]
                    *reinterpret_cast<uint32_t*>(P + rowoff) = hp;
                    *reinterpret_cast<uint32_t*>(P + rowoff + CDIM) = hp;
                    *reinterpret_cast<uint32_t*>(P + rowoff + 2 * CDIM) = lp;
                } else {        // pc: [hi, lo, hi]
                    *reinterpret_cast<uint32_t*>(P + rowoff) = hp;
                    *reinterpret_cast<uint32_t*>(P + rowoff + CDIM) = lp;
                    *reinterpret_cast<uint32_t*>(P + rowoff + 2 * CDIM) = hp;
                }
            }
        }
    }
}

// ============================================================
// K4: score GEMM (HMMA, 64x64 tiles, 256 thr, 2x4 warps, 3-stage)
// ============================================================
__global__ void __launch_bounds__(256) score_hmma() {
    __shared__ __align__(16) __nv_bfloat16 sm[6 * SMAT];

    const int tid = threadIdx.x;
    const int b = blockIdx.z;
    const int i0 = blockIdx.y * 64;
    const int j0 = blockIdx.x * 64;

    const __nv_bfloat16* A = g_pt_s + (size_t)(b * LDIM + i0) * KSPL;
    const __nv_bfloat16* B = g_pc_s + (size_t)(b * LDIM + j0) * KSPL;

    float acc[4][4];
    #pragma unroll
    for (int i = 0; i < 4; i++)
        acc[i][0] = acc[i][1] = acc[i][2] = acc[i][3] = 0.0f;

    hmma_loop64<2, 4, 256>(A, B, sm, acc, tid);

    const int lane = tid & 31;
    const int warp = tid >> 5;
    const int wm = warp % 2;
    const int wn = warp / 2;

    float lsum = 0.0f;
    float* Sb = g_scores + ((size_t)b << 16);
    #pragma unroll
    for (int im = 0; im < 2; im++) {
        #pragma unroll
        for (int jn = 0; jn < 2; jn++) {
            const float* c = acc[im * 2 + jn];
            int j = j0 + wn * 16 + jn * 8 + (lane & 3) * 2;
            int r0 = i0 + wm * 32 + im * 16 + (lane >> 2);
            #pragma unroll
            for (int h = 0; h < 2; h++) {
                int i = r0 + h * 8;
                float s0 = sigmoid_fast(c[2 * h + 0]);
                float s1 = sigmoid_fast(c[2 * h + 1]);
                *reinterpret_cast<float2*>(Sb + (size_t)i * LDIM + j) =
                    make_float2(s0, s1);
                lsum += s0 + s1;
            }
        }
    }
    #pragma unroll
    for (int off = 16; off; off >>= 1)
        lsum += __shfl_xor_sync(0xFFFFFFFFu, lsum, off);
    __shared__ float red[8];
    if (lane == 0) red[warp] = lsum;
    __syncthreads();
    if (tid == 0) {
        float s = 0.0f;
        #pragma unroll
        for (int w = 0; w < 8; w++) s += red[w];
        atomicAdd(&g_Ssum[b], s);
    }
}

// ============================================================
// K5: cp_unnorm[b,c] = sum_{i,j} tanh(xd[b,i,c]*xt[b,j,c]) * scores[b,i,j]
// Pure MUFU.TANH (round-7 form; proven at the MUFU floor).
// ============================================================
__global__ void __launch_bounds__(512) cp_kernel(const float* __restrict__ xd,
                                                 const float* __restrict__ xt) {
    const int b = blockIdx.y;
    const int i0 = blockIdx.x * 4;
    const int c = threadIdx.x;

    __shared__ float4 ws4[LDIM];
    {
        float* wsf = reinterpret_cast<float*>(ws4);
        const float* src = g_scores + (size_t)b * LDIM * LDIM + (size_t)i0 * LDIM;
        for (int t = threadIdx.x; t < 4 * LDIM; t += 512) {
            int i = t >> 8, j = t & (LDIM - 1);
            wsf[(j << 2) | i] = src[i * LDIM + j];
        }
    }

    const float* xdp = xd + ((size_t)(b * LDIM + i0)) * CDIM + c;
    const float xd0 = xdp[0 * CDIM];
    const float xd1 = xdp[1 * CDIM];
    const float xd2 = xdp[2 * CDIM];
    const float xd3 = xdp[3 * CDIM];
    __syncthreads();

    const float* xtp = xt + ((size_t)(b * LDIM)) * CDIM + c;
    float acc = 0.0f;
    #pragma unroll 4
    for (int j = 0; j < LDIM; j++) {
        float xtv = __ldg(&xtp[(size_t)j * CDIM]);
        float4 w = ws4[j];
        acc = fmaf(tanh_mufu(xd0 * xtv), w.x, acc);
        acc = fmaf(tanh_mufu(xd1 * xtv), w.y, acc);
        acc = fmaf(tanh_mufu(xd2 * xtv), w.z, acc);
        acc = fmaf(tanh_mufu(xd3 * xtv), w.w, acc);
    }
    atomicAdd(&g_cp[b * CDIM + c], acc);
}

// ============================================================
// K6: out[b,o] += (cp[b,:]/S_b) @ Wf[:,o]
// ============================================================
__global__ void out_gemm(const float* __restrict__ Wf, float* __restrict__ out) {
    const int b = blockIdx.x;
    const int c0 = blockIdx.y * 128;
    const int o = threadIdx.x;

    __shared__ float cps[128];
    float inv = __fdividef(1.0f, g_Ssum[b]);
    if (threadIdx.x < 128)
        cps[threadIdx.x] = g_cp[b * CDIM + c0 + threadIdx.x] * inv;
    __syncthreads();

    float acc = 0.0f;
    #pragma unroll 8
    for (int cc = 0; cc < 128; cc++)
        acc = fmaf(cps[cc], Wf[(c0 + cc) * ODIM + o], acc);
    atomicAdd(&out[b * ODIM + o], acc);
}

// ============================================================
extern "C" void kernel_launch(void* const* d_in, const int* in_sizes, int n_in,
                              void* d_out, int out_size) {
    const float* xd = (const float*)d_in[0];
    const float* xt = (const float*)d_in[1];
    const float* Wc = (const float*)d_in[2];
    const float* bc = (const float*)d_in[3];
    const float* Wp = (const float*)d_in[4];
    const float* bp = (const float*)d_in[5];
    const float* Wf = (const float*)d_in[6];
    const float* bf = (const float*)d_in[7];
    float* out = (float*)d_out;

    init_kernel<<<8, 512>>>(bf, out);
    split_x_kernel<<<dim3(MTOT * CDIM / 4 / 256, 1, 2), 256>>>(xt, xd);
    split_w_kernel<<<dim3(16, 16, 2), dim3(32, 32)>>>(Wp, Wc);
    proj_hmma<<<dim3(CDIM / 64, MTOT / 64, 2), 256>>>(bp, bc);
    score_hmma<<<dim3(LDIM / 64, LDIM / 64, BDIM), 256>>>();
    cp_kernel<<<dim3(LDIM / 4, BDIM), 512>>>(xd, xt);
    out_gemm<<<dim3(BDIM, 4), 512>>>(Wf, out);
}

// round 14
// speedup vs baseline: 1.0643x; 1.0331x over previous
#include <cuda_runtime.h>
#include <cuda_bf16.h>
#include <cstdint>

#define BDIM 8
#define LDIM 256
#define CDIM 512
#define ODIM 512
#define MTOT (BDIM * LDIM)   // 2048
#define KSPL 1536            // 3*CDIM split-K
#define SROWP 72             // smem row stride (64 + 8 pad) bf16

// -------- scratch (static device globals; no allocation) --------
__device__ __align__(16) __nv_bfloat16 g_xt_s[MTOT * KSPL];   // relu(xt) split [hi,hi,lo]
__device__ __align__(16) __nv_bfloat16 g_xd_s[MTOT * KSPL];   // relu(xd) split [hi,hi,lo]
__device__ __align__(16) __nv_bfloat16 g_Wp_s[CDIM * KSPL];   // Wp^T split [hi,lo,hi]
__device__ __align__(16) __nv_bfloat16 g_Wc_s[CDIM * KSPL];   // Wc^T split [hi,lo,hi]
__device__ __align__(16) __nv_bfloat16 g_pt_s[MTOT * KSPL];   // pt split [hi,hi,lo]
__device__ __align__(16) __nv_bfloat16 g_pc_s[MTOT * KSPL];   // pc split [hi,lo,hi]
__device__ float g_scores[BDIM * LDIM * LDIM];
__device__ float g_Ssum[BDIM];
__device__ float g_cp[BDIM * CDIM];

// -------- transcendentals --------
__device__ __forceinline__ float tanh_mufu(float x) {
    float y;
    asm("tanh.approx.f32 %0, %1;" : "=f"(y) : "f"(x));
    return y;
}
__device__ __forceinline__ float sigmoid_fast(float x) {
    return __fdividef(1.0f, 1.0f + __expf(-x));
}

// -------- helpers --------
__device__ __forceinline__ uint32_t smem_u32(const void* p) {
    uint32_t a;
    asm("{ .reg .u64 t; cvta.to.shared.u64 t, %1; cvt.u32.u64 %0, t; }" : "=r"(a) : "l"(p));
    return a;
}
__device__ __forceinline__ void ldsm4(uint32_t* r, uint32_t addr) {
    asm volatile("ldmatrix.sync.aligned.m8n8.x4.shared.b16 {%0,%1,%2,%3}, [%4];"
                 : "=r"(r[0]), "=r"(r[1]), "=r"(r[2]), "=r"(r[3]) : "r"(addr));
}
__device__ __forceinline__ void mma_bf16(float* c, const uint32_t* a,
                                         uint32_t b0, uint32_t b1) {
    asm volatile(
        "mma.sync.aligned.m16n8k16.row.col.f32.bf16.bf16.f32 "
        "{%0,%1,%2,%3}, {%4,%5,%6,%7}, {%8,%9}, {%0,%1,%2,%3};"
        : "+f"(c[0]), "+f"(c[1]), "+f"(c[2]), "+f"(c[3])
        : "r"(a[0]), "r"(a[1]), "r"(a[2]), "r"(a[3]), "r"(b0), "r"(b1));
}
__device__ __forceinline__ void cp_async16(uint32_t dst, const void* src) {
    asm volatile("cp.async.ca.shared.global [%0], [%1], 16;" :: "r"(dst), "l"(src));
}
#define CP_COMMIT() asm volatile("cp.async.commit_group;" ::: "memory")
#define CP_WAIT1()  asm volatile("cp.async.wait_group 1;" ::: "memory")
#define CP_WAIT0()  asm volatile("cp.async.wait_group 0;" ::: "memory")

__device__ __forceinline__ void split2(float v, unsigned short& h, unsigned short& l) {
    __nv_bfloat16 hb = __float2bfloat16(v);
    __nv_bfloat16 lb = __float2bfloat16(v - __bfloat162float(hb));
    h = __bfloat16_as_ushort(hb);
    l = __bfloat16_as_ushort(lb);
}

// ============================================================
// HMMA mainloop: C[BM,64] += A[BM,K'] . B[64,K']^T over K'=1536, BK=64,
// 3-stage cp.async pipeline, ONE __syncthreads per chunk.
// smem per stage: A (BM rows) then B (64 rows), SROWP stride.
// NWM x NWN warps; warp tile (BM/NWM) x (64/NWN).
// ============================================================
template <int BM, int NWM, int NWN, int NT>
__device__ __forceinline__ void hmma_loop(
        const __nv_bfloat16* __restrict__ A0,
        const __nv_bfloat16* __restrict__ B0,
        __nv_bfloat16* sm, float (*acc)[4], int tid) {
    constexpr int MI = BM / NWM / 16;
    constexpr int NJ = 64 / NWN / 8;
    constexpr int NJ2 = NJ / 2;
    constexpr int STAGE = (BM + 64) * SROWP;      // elems per stage
    constexpr int NLD = (BM + 64) * 8;            // uint4 loads per stage
    constexpr int LPT = NLD / NT;
    constexpr int NCH = KSPL / 64;                // 24

    const int lane = tid & 31;
    const int warp = tid >> 5;
    const int wm = warp % NWM;
    const int wn = warp / NWM;
    const uint32_t base = smem_u32(sm);

    auto issue = [&](int s, int c) {
        #pragma unroll
        for (int q = 0; q < LPT; q++) {
            int idx = tid + q * NT;
            int matB = (idx >= BM * 8);
            int rem = matB ? (idx - BM * 8) : idx;
            int row = rem >> 3;
            int kq = rem & 7;
            const __nv_bfloat16* g = (matB ? B0 : A0) + (size_t)row * KSPL + c * 64 + kq * 8;
            uint32_t d = base + (uint32_t)(s * STAGE + matB * (BM * SROWP)
                                           + row * SROWP + kq * 8) * 2;
            cp_async16(d, g);
        }
        CP_COMMIT();
    };

    issue(0, 0);
    issue(1, 1);

    for (int c = 0; c < NCH; c++) {
        const int s = c % 3;
        if (c + 1 < NCH) CP_WAIT1(); else CP_WAIT0();
        __syncthreads();   // chunk c visible; compute of c-1 retired by all warps
        if (c + 2 < NCH) issue((c + 2) % 3, c + 2);

        const uint32_t aBase = base + (uint32_t)(s * STAGE) * 2;
        const uint32_t bBase = aBase + (uint32_t)(BM * SROWP) * 2;
        #pragma unroll
        for (int kk = 0; kk < 64; kk += 16) {
            uint32_t af[MI][4];
            #pragma unroll
            for (int im = 0; im < MI; im++) {
                int row = wm * (BM / NWM) + im * 16 + (lane & 15);
                ldsm4(af[im], aBase + (uint32_t)(row * SROWP + kk + (lane >> 4) * 8) * 2);
            }
            #pragma unroll
            for (int j2 = 0; j2 < NJ2; j2++) {
                uint32_t bfr[4];
                int row = wn * (64 / NWN) + j2 * 16 + (lane & 15);
                ldsm4(bfr, bBase + (uint32_t)(row * SROWP + kk + (lane >> 4) * 8) * 2);
                #pragma unroll
                for (int im = 0; im < MI; im++) {
                    mma_bf16(acc[im * NJ + 2 * j2 + 0], af[im], bfr[0], bfr[2]);
                    mma_bf16(acc[im * NJ + 2 * j2 + 1], af[im], bfr[1], bfr[3]);
                }
            }
        }
    }
    __syncthreads();
}

// ============================================================
// K0: init
// ============================================================
__global__ void init_kernel(const float* __restrict__ bf, float* __restrict__ out) {
    int idx = blockIdx.x * blockDim.x + threadIdx.x;
    if (idx < BDIM) g_Ssum[idx] = 0.0f;
    if (idx < BDIM * CDIM) {
        g_cp[idx] = 0.0f;
        out[idx] = bf[idx & (ODIM - 1)];
    }
}

// ============================================================
// K1: split X (with relu) -> [hi, hi, lo] bf16, K'=1536
// ============================================================
__global__ void split_x_kernel(const float* __restrict__ xt, const float* __restrict__ xd) {
    const float* X = blockIdx.z ? xd : xt;
    __nv_bfloat16* O = blockIdx.z ? g_xd_s : g_xt_s;
    int gid = blockIdx.x * blockDim.x + threadIdx.x;
    if (gid >= MTOT * CDIM / 4) return;
    int m = gid >> 7;
    int k4 = (gid & 127) * 4;
    float4 v = *reinterpret_cast<const float4*>(X + (size_t)m * CDIM + k4);
    float vv[4] = {fmaxf(v.x, 0.f), fmaxf(v.y, 0.f), fmaxf(v.z, 0.f), fmaxf(v.w, 0.f)};
    unsigned short h[4], l[4];
    #pragma unroll
    for (int i = 0; i < 4; i++) split2(vv[i], h[i], l[i]);
    uint2 hp = make_uint2((uint32_t)h[0] | ((uint32_t)h[1] << 16),
                          (uint32_t)h[2] | ((uint32_t)h[3] << 16));
    uint2 lp = make_uint2((uint32_t)l[0] | ((uint32_t)l[1] << 16),
                          (uint32_t)l[2] | ((uint32_t)l[3] << 16));
    size_t base = (size_t)m * KSPL + k4;
    *reinterpret_cast<uint2*>(O + base) = hp;
    *reinterpret_cast<uint2*>(O + base + CDIM) = hp;
    *reinterpret_cast<uint2*>(O + base + 2 * CDIM) = lp;
}

// ============================================================
// K2: split W with transpose: W[k,n] -> Wsplit[n,k'] segs [hi, lo, hi]
// ============================================================
__global__ void split_w_kernel(const float* __restrict__ Wp, const float* __restrict__ Wc) {
    const float* W = blockIdx.z ? Wc : Wp;
    __nv_bfloat16* O = blockIdx.z ? g_Wc_s : g_Wp_s;
    __shared__ float tile[32][33];
    int k0 = blockIdx.x * 32, n0 = blockIdx.y * 32;
    int tx = threadIdx.x, ty = threadIdx.y;
    tile[ty][tx] = W[(size_t)(k0 + ty) * CDIM + n0 + tx];
    __syncthreads();
    float v = tile[tx][ty];
    unsigned short h, l;
    split2(v, h, l);
    size_t base = (size_t)(n0 + ty) * KSPL + k0 + tx;
    O[base] = __ushort_as_bfloat16(h);
    O[base + CDIM] = __ushort_as_bfloat16(l);
    O[base + 2 * CDIM] = __ushort_as_bfloat16(h);
}

// ============================================================
// K3: projection GEMMs (HMMA, BM=128 x BN=64, 256 thr, 4x2 warps,
// 32x32 warp tiles, 3-stage).  z=0: pt [hi,hi,lo] ; z=1: pc [hi,lo,hi]
// ============================================================
__global__ void __launch_bounds__(256) proj_hmma(const float* __restrict__ bp,
                                                 const float* __restrict__ bc) {
    __shared__ __align__(16) __nv_bfloat16 sm[3 * (128 + 64) * SROWP];   // ~83 KB

    const int tid = threadIdx.x;
    const int z = blockIdx.z;
    const int m0 = blockIdx.y * 128;
    const int n0 = blockIdx.x * 64;

    const __nv_bfloat16* X = z ? g_xd_s : g_xt_s;
    const __nv_bfloat16* Wm = z ? g_Wc_s : g_Wp_s;
    const float* bias = z ? bc : bp;
    __nv_bfloat16* P = z ? g_pc_s : g_pt_s;

    float acc[8][4];   // MI=2, NJ=4
    #pragma unroll
    for (int i = 0; i < 8; i++)
        acc[i][0] = acc[i][1] = acc[i][2] = acc[i][3] = 0.0f;

    hmma_loop<128, 4, 2, 256>(X + (size_t)m0 * KSPL, Wm + (size_t)n0 * KSPL, sm, acc, tid);

    const int lane = tid & 31;
    const int warp = tid >> 5;
    const int wm = warp % 4;    // 0..3 (32-row groups)
    const int wn = warp / 4;    // 0..1 (32-col groups)

    #pragma unroll
    for (int im = 0; im < 2; im++) {
        #pragma unroll
        for (int jn = 0; jn < 4; jn++) {
            const float* c = acc[im * 4 + jn];
            int n = n0 + wn * 32 + jn * 8 + (lane & 3) * 2;
            float b0 = __ldg(&bias[n]), b1 = __ldg(&bias[n + 1]);
            int r0 = m0 + wm * 32 + im * 16 + (lane >> 2);
            #pragma unroll
            for (int h = 0; h < 2; h++) {
                int m = r0 + h * 8;
                float v0 = c[2 * h + 0] + b0;
                float v1 = c[2 * h + 1] + b1;
                unsigned short h0, l0, h1, l1;
                split2(v0, h0, l0);
                split2(v1, h1, l1);
                uint32_t hp = (uint32_t)h0 | ((uint32_t)h1 << 16);
                uint32_t lp = (uint32_t)l0 | ((uint32_t)l1 << 16);
                size_t rowoff = (size_t)m * KSPL + n;
                if (z == 0) {   // pt: [hi, hi, lo]
                    *reinterpret_cast<uint32_t*>(P + rowoff) = hp;
                    *reinterpret_cast<uint32_t*>(P + rowoff + CDIM) = hp;
                    *reinterpret_cast<uint32_t*>(P + rowoff + 2 * CDIM) = lp;
                } else {        // pc: [hi, lo, hi]
                    *reinterpret_cast<uint32_t*>(P + rowoff) = hp;
                    *reinterpret_cast<uint32_t*>(P + rowoff + CDIM) = lp;
                    *reinterpret_cast<uint32_t*>(P + rowoff + 2 * CDIM) = hp;
                }
            }
        }
    }
}

// ============================================================
// K4: score GEMM (HMMA, 64x64 tiles, 256 thr, 2x4 warps, 3-stage)
// ============================================================
__global__ void __launch_bounds__(256) score_hmma() {
    __shared__ __align__(16) __nv_bfloat16 sm[3 * (64 + 64) * SROWP];

    const int tid = threadIdx.x;
    const int b = blockIdx.z;
    const int i0 = blockIdx.y * 64;
    const int j0 = blockIdx.x * 64;

    const __nv_bfloat16* A = g_pt_s + (size_t)(b * LDIM + i0) * KSPL;
    const __nv_bfloat16* B = g_pc_s + (size_t)(b * LDIM + j0) * KSPL;

    float acc[4][4];   // MI=2, NJ=2
    #pragma unroll
    for (int i = 0; i < 4; i++)
        acc[i][0] = acc[i][1] = acc[i][2] = acc[i][3] = 0.0f;

    hmma_loop<64, 2, 4, 256>(A, B, sm, acc, tid);

    const int lane = tid & 31;
    const int warp = tid >> 5;
    const int wm = warp % 2;
    const int wn = warp / 2;

    float lsum = 0.0f;
    float* Sb = g_scores + ((size_t)b << 16);
    #pragma unroll
    for (int im = 0; im < 2; im++) {
        #pragma unroll
        for (int jn = 0; jn < 2; jn++) {
            const float* c = acc[im * 2 + jn];
            int j = j0 + wn * 16 + jn * 8 + (lane & 3) * 2;
            int r0 = i0 + wm * 32 + im * 16 + (lane >> 2);
            #pragma unroll
            for (int h = 0; h < 2; h++) {
                int i = r0 + h * 8;
                float s0 = sigmoid_fast(c[2 * h + 0]);
                float s1 = sigmoid_fast(c[2 * h + 1]);
                *reinterpret_cast<float2*>(Sb + (size_t)i * LDIM + j) =
                    make_float2(s0, s1);
                lsum += s0 + s1;
            }
        }
    }
    #pragma unroll
    for (int off = 16; off; off >>= 1)
        lsum += __shfl_xor_sync(0xFFFFFFFFu, lsum, off);
    __shared__ float red[8];
    if (lane == 0) red[warp] = lsum;
    __syncthreads();
    if (tid == 0) {
        float s = 0.0f;
        #pragma unroll
        for (int w = 0; w < 8; w++) s += red[w];
        atomicAdd(&g_Ssum[b], s);
    }
}

// ============================================================
// K5: cp_unnorm[b,c] = sum_{i,j} tanh(xd[b,i,c]*xt[b,j,c]) * scores[b,i,j]
// Pure MUFU.TANH (proven at the MUFU floor).
// ============================================================
__global__ void __launch_bounds__(512) cp_kernel(const float* __restrict__ xd,
                                                 const float* __restrict__ xt) {
    const int b = blockIdx.y;
    const int i0 = blockIdx.x * 4;
    const int c = threadIdx.x;

    __shared__ float4 ws4[LDIM];
    {
        float* wsf = reinterpret_cast<float*>(ws4);
        const float* src = g_scores + (size_t)b * LDIM * LDIM + (size_t)i0 * LDIM;
        for (int t = threadIdx.x; t < 4 * LDIM; t += 512) {
            int i = t >> 8, j = t & (LDIM - 1);
            wsf[(j << 2) | i] = src[i * LDIM + j];
        }
    }

    const float* xdp = xd + ((size_t)(b * LDIM + i0)) * CDIM + c;
    const float xd0 = xdp[0 * CDIM];
    const float xd1 = xdp[1 * CDIM];
    const float xd2 = xdp[2 * CDIM];
    const float xd3 = xdp[3 * CDIM];
    __syncthreads();

    const float* xtp = xt + ((size_t)(b * LDIM)) * CDIM + c;
    float acc = 0.0f;
    #pragma unroll 4
    for (int j = 0; j < LDIM; j++) {
        float xtv = __ldg(&xtp[(size_t)j * CDIM]);
        float4 w = ws4[j];
        acc = fmaf(tanh_mufu(xd0 * xtv), w.x, acc);
        acc = fmaf(tanh_mufu(xd1 * xtv), w.y, acc);
        acc = fmaf(tanh_mufu(xd2 * xtv), w.z, acc);
        acc = fmaf(tanh_mufu(xd3 * xtv), w.w, acc);
    }
    atomicAdd(&g_cp[b * CDIM + c], acc);
}

// ============================================================
// K6: out[b,o] += (cp[b,:]/S_b) @ Wf[:,o]
// ============================================================
__global__ void out_gemm(const float* __restrict__ Wf, float* __restrict__ out) {
    const int b = blockIdx.x;
    const int c0 = blockIdx.y * 128;
    const int o = threadIdx.x;

    __shared__ float cps[128];
    float inv = __fdividef(1.0f, g_Ssum[b]);
    if (threadIdx.x < 128)
        cps[threadIdx.x] = g_cp[b * CDIM + c0 + threadIdx.x] * inv;
    __syncthreads();

    float acc = 0.0f;
    #pragma unroll 8
    for (int cc = 0; cc < 128; cc++)
        acc = fmaf(cps[cc], Wf[(c0 + cc) * ODIM + o], acc);
    atomicAdd(&out[b * ODIM + o], acc);
}

// ============================================================
extern "C" void kernel_launch(void* const* d_in, const int* in_sizes, int n_in,
                              void* d_out, int out_size) {
    const float* xd = (const float*)d_in[0];
    const float* xt = (const float*)d_in[1];
    const float* Wc = (const float*)d_in[2];
    const float* bc = (const float*)d_in[3];
    const float* Wp = (const float*)d_in[4];
    const float* bp = (const float*)d_in[5];
    const float* Wf = (const float*)d_in[6];
    const float* bf = (const float*)d_in[7];
    float* out = (float*)d_out;

    init_kernel<<<8, 512>>>(bf, out);
    split_x_kernel<<<dim3(MTOT * CDIM / 4 / 256, 1, 2), 256>>>(xt, xd);
    split_w_kernel<<<dim3(16, 16, 2), dim3(32, 32)>>>(Wp, Wc);
    proj_hmma<<<dim3(CDIM / 64, MTOT / 128, 2), 256>>>(bp, bc);
    score_hmma<<<dim3(LDIM / 64, LDIM / 64, BDIM), 256>>>();
    cp_kernel<<<dim3(LDIM / 4, BDIM), 512>>>(xd, xt);
    out_gemm<<<dim3(BDIM, 4), 512>>>(Wf, out);
}